// round 3
// baseline (speedup 1.0000x reference)
#include <cuda_runtime.h>
#include <cstdint>

#define KCODES 1024
#define DIM 64
#define N_ROWS 65536
#define CHUNK 128
#define NCHUNK (KCODES / CHUNK)

typedef unsigned long long ull;

// Scratch (no device allocation allowed -> __device__ globals)
__device__ int    g_idx[N_ROWS];
__device__ int    g_counts[KCODES];
__device__ float  g_Esq[KCODES];
__device__ double g_loss;

// Packed fp32x2 ops (sm_100+). FFMA2 doubles fp32 throughput vs scalar FFMA.
#define FMA2(acc, x, y) asm("fma.rn.f32x2 %0, %1, %2, %0;" : "+l"(acc) : "l"(x), "l"(y))
#define ADD2(r, x, y)   asm("add.rn.f32x2 %0, %1, %2;"     : "=l"(r)   : "l"(x), "l"(y))

// ---------------------------------------------------------------------------
// Kernel 1: per-code squared norms + zero the histogram / loss accumulator.
// ---------------------------------------------------------------------------
__global__ void prep_kernel(const float* __restrict__ E) {
    int k = blockIdx.x * blockDim.x + threadIdx.x;
    if (k < KCODES) {
        float s = 0.f;
        #pragma unroll
        for (int d = 0; d < DIM; d++) {
            float v = E[k * DIM + d];
            s = fmaf(v, v, s);
        }
        g_Esq[k] = s;
        g_counts[k] = 0;
    }
    if (k == 0) g_loss = 0.0;
}

// ---------------------------------------------------------------------------
// Kernel 2: argmin over codes, bit-mimicking the reference's rounding chain:
//   d = fl( fl(zsq + esq_k) - 2*s_k )
// (verified bit-exact vs the JAX reference in R2: rel_err == 0.0).
// 1 row/thread, 256 threads/block, 2 CTAs/SM -> 4 warps/SMSP so the per-k
// reduction tail (~35 dependent cycles) and LDS latency are hidden by
// sibling warps; k-loop unrolled x2 for cross-iteration ILP.
// ---------------------------------------------------------------------------
__global__ void __launch_bounds__(256, 2)
argmin_kernel(const float* __restrict__ in, const float* __restrict__ E) {
    __shared__ __align__(16) float sE[CHUNK * DIM];
    __shared__ float sEsq[CHUNK];

    const int t = threadIdx.x;
    const int n = blockIdx.x * 256 + t;
    const int b = n >> 10, p = n & 1023;
    const float* zp = in + b * 65536 + p;

    // Load + pack z into 32 f32x2 registers; accumulate zsq (same op order as
    // R2 -> argmin-neutral anyway, zsq shifts all d_k by grid-aligned amounts).
    ull zA[32];
    float zsq = 0.f;
    #pragma unroll
    for (int i = 0; i < 32; i++) {
        float a0 = zp[(2 * i) * 1024];
        float a1 = zp[(2 * i + 1) * 1024];
        zsq = fmaf(a0, a0, zsq);
        zsq = fmaf(a1, a1, zsq);
        zA[i] = (ull)__float_as_uint(a0) | ((ull)__float_as_uint(a1) << 32);
    }

    float best = 3.4e38f;
    int bi = 0;

    for (int c = 0; c < NCHUNK; c++) {
        __syncthreads();
        // Stage 128 codes (32 KB) into smem, float4-wide, fully coalesced.
        const float4* src = (const float4*)(E + c * CHUNK * DIM);
        float4* dst = (float4*)sE;
        #pragma unroll
        for (int i = 0; i < 8; i++) dst[t + i * 256] = src[t + i * 256];
        if (t < CHUNK) sEsq[t] = g_Esq[c * CHUNK + t];
        __syncthreads();

        #pragma unroll 2
        for (int k = 0; k < CHUNK; k++) {
            const ulonglong2* e2 = (const ulonglong2*)(sE + k * DIM);
            ull a0 = 0, a1 = 0;  // 2 independent FMA chains (lat4/rt2 -> enough)
            #pragma unroll
            for (int j = 0; j < 16; j++) {
                ulonglong2 ee = e2[j];            // ld.shared.v2.u64 (broadcast)
                FMA2(a0, zA[2 * j],     ee.x);
                FMA2(a1, zA[2 * j + 1], ee.y);
            }
            ull sa;
            ADD2(sa, a0, a1);
            float s0 = __fadd_rn(__uint_as_float((unsigned)sa),
                                 __uint_as_float((unsigned)(sa >> 32)));
            float esq = sEsq[k];
            // Reference rounding chain: t = fl(zsq + esq); d = fl(t - 2s).
            float t0 = __fadd_rn(zsq, esq);
            float d0 = __fmaf_rn(-2.0f, s0, t0);
            int kk = c * CHUNK + k;
            if (d0 < best) { best = d0; bi = kk; }  // strict < keeps first min
        }
    }

    g_idx[n] = bi;
    atomicAdd(&g_counts[bi], 1);
}

// ---------------------------------------------------------------------------
// Kernel 3: gather Zq (straight-through, bit-mimicking fl(z + fl(e - z))),
// write transposed [B,C,H,W], accumulate sum((e - z)^2) for the losses.
// ---------------------------------------------------------------------------
__global__ void gather_kernel(const float* __restrict__ in,
                              const float* __restrict__ E,
                              float* __restrict__ out) {
    const int t = threadIdx.x;
    const int n = blockIdx.x * 256 + t;
    const int b = n >> 10, p = n & 1023;
    const int id = g_idx[n];

    float e[DIM];
    const float4* er = (const float4*)(E + id * DIM);
    #pragma unroll
    for (int i = 0; i < 16; i++) {
        float4 v = er[i];
        e[4 * i] = v.x; e[4 * i + 1] = v.y; e[4 * i + 2] = v.z; e[4 * i + 3] = v.w;
    }

    const float* zp = in + b * 65536 + p;
    float* zq = out + 1 + b * 65536 + p;  // Zq starts at out[1]
    float ls = 0.f;
    #pragma unroll
    for (int d = 0; d < DIM; d++) {
        float z = zp[d * 1024];
        float diff = __fsub_rn(e[d], z);          // ref: Zq_t - Ze_t in fp32
        ls = fmaf(diff, diff, ls);
        zq[d * 1024] = __fadd_rn(z, diff);        // ref: Ze + (Zq - Ze) in fp32
    }

    // Block-reduce loss partial, one double atomic per block.
    ls += __shfl_xor_sync(0xffffffffu, ls, 16);
    ls += __shfl_xor_sync(0xffffffffu, ls, 8);
    ls += __shfl_xor_sync(0xffffffffu, ls, 4);
    ls += __shfl_xor_sync(0xffffffffu, ls, 2);
    ls += __shfl_xor_sync(0xffffffffu, ls, 1);
    __shared__ float warpsum[8];
    if ((t & 31) == 0) warpsum[t >> 5] = ls;
    __syncthreads();
    if (t == 0) {
        float s = 0.f;
        #pragma unroll
        for (int w = 0; w < 8; w++) s += warpsum[w];
        atomicAdd(&g_loss, (double)s);
    }
}

// ---------------------------------------------------------------------------
// Kernel 4: perplexity from histogram + scalar outputs.
// ---------------------------------------------------------------------------
__global__ void finalize_kernel(float* __restrict__ out) {
    __shared__ float red[32];
    const int t = threadIdx.x;  // 1024 threads
    float cnt = (float)g_counts[t];
    float p = cnt * (1.0f / 65536.0f);
    float v = p * log2f(p + 1e-10f);

    v += __shfl_xor_sync(0xffffffffu, v, 16);
    v += __shfl_xor_sync(0xffffffffu, v, 8);
    v += __shfl_xor_sync(0xffffffffu, v, 4);
    v += __shfl_xor_sync(0xffffffffu, v, 2);
    v += __shfl_xor_sync(0xffffffffu, v, 1);
    if ((t & 31) == 0) red[t >> 5] = v;
    __syncthreads();
    if (t < 32) {
        float x = red[t];
        x += __shfl_xor_sync(0xffffffffu, x, 16);
        x += __shfl_xor_sync(0xffffffffu, x, 8);
        x += __shfl_xor_sync(0xffffffffu, x, 4);
        x += __shfl_xor_sync(0xffffffffu, x, 2);
        x += __shfl_xor_sync(0xffffffffu, x, 1);
        if (t == 0) {
            float entropy = -x;
            float perp = exp2f(entropy);
            float l = (float)(g_loss * (1.0 / 4194304.0));  // mean over B*H*W*D
            out[0] = l + 0.25f * l;          // q + BETA*e (q == e numerically)
            out[1 + N_ROWS * DIM]     = l;   // e_latent_loss
            out[1 + N_ROWS * DIM + 1] = l;   // q_latent_loss
            out[1 + N_ROWS * DIM + 2] = perp;
        }
    }
}

// ---------------------------------------------------------------------------
extern "C" void kernel_launch(void* const* d_in, const int* in_sizes, int n_in,
                              void* d_out, int out_size) {
    const float* in = (const float*)d_in[0];
    const float* E  = (const float*)d_in[1];
    float* out = (float*)d_out;

    prep_kernel<<<4, 256>>>(E);
    argmin_kernel<<<256, 256>>>(in, E);
    gather_kernel<<<256, 256>>>(in, E, out);
    finalize_kernel<<<1, 1024>>>(out);
}

// round 5
// speedup vs baseline: 1.2846x; 1.2846x over previous
#include <cuda_runtime.h>
#include <cstdint>

#define KCODES 1024
#define DIM 64
#define N_ROWS 65536
#define CHUNK 128
#define NCHUNK (KCODES / CHUNK)

typedef unsigned long long ull;

// Scratch (no device allocation allowed -> __device__ globals)
__device__ int    g_idx[N_ROWS];
__device__ int    g_counts[KCODES];
__device__ float  g_Esq[KCODES];
__device__ double g_loss;

// Packed fp32x2 ops (sm_100+). FFMA2 doubles fp32 throughput vs scalar FFMA.
#define FMA2(acc, x, y) asm("fma.rn.f32x2 %0, %1, %2, %0;" : "+l"(acc) : "l"(x), "l"(y))
#define ADD2(r, x, y)   asm("add.rn.f32x2 %0, %1, %2;"     : "=l"(r)   : "l"(x), "l"(y))

// ---------------------------------------------------------------------------
// Kernel 1: per-code squared norms + zero the histogram / loss accumulator.
// ---------------------------------------------------------------------------
__global__ void prep_kernel(const float* __restrict__ E) {
    int k = blockIdx.x * blockDim.x + threadIdx.x;
    if (k < KCODES) {
        float s = 0.f;
        #pragma unroll
        for (int d = 0; d < DIM; d++) {
            float v = E[k * DIM + d];
            s = fmaf(v, v, s);
        }
        g_Esq[k] = s;
        g_counts[k] = 0;
    }
    if (k == 0) g_loss = 0.0;
}

// ---------------------------------------------------------------------------
// Kernel 2: argmin over codes. Bit-exact reproduction of the reference
// rounding chain (verified rel_err == 0.0 in R2):
//   per dot: 2 packed accs -> ADD2 -> fadd(lo,hi); d = fma(-2, s, fl(zsq+esq))
// DO NOT change the reduction order.
// CRITICAL (R4 lesson): the k-scan MUST be in ascending code order. The
// reference's d values are quantized to a ~3.8e-6 grid, so exact ties across
// codes DO occur; jnp.argmin takes the lowest index, which strict '<' only
// reproduces under an ascending scan. No chunk reordering/stagger.
// Layout: 128 thr, 2 rows/thread (16 LDS feed 128 FFMA2 per k-pair),
// k-loop unrolled x2 so each code's reduction tail hides under the next
// code's FMA stream; branchless FMNMX min.
// ---------------------------------------------------------------------------
__global__ void __launch_bounds__(128, 2)
argmin_kernel(const float* __restrict__ in, const float* __restrict__ E) {
    __shared__ __align__(16) float sE[CHUNK * DIM];
    __shared__ float sEsq[CHUNK];

    const int t = threadIdx.x;
    const int base = blockIdx.x * 256;
    const int n0 = base + t;
    const int n1 = n0 + 128;
    const int b0 = n0 >> 10, p0 = n0 & 1023;
    const int b1 = n1 >> 10, p1 = n1 & 1023;
    const float* z0p = in + b0 * 65536 + p0;
    const float* z1p = in + b1 * 65536 + p1;

    // Load + pack both z vectors into f32x2 registers; accumulate zsq
    // (zsq order is argmin-neutral: it shifts all d_k of a row equally).
    ull zA[32], zB[32];
    float zsq0 = 0.f, zsq1 = 0.f;
    #pragma unroll
    for (int i = 0; i < 32; i++) {
        float a0 = z0p[(2 * i) * 1024];
        float a1 = z0p[(2 * i + 1) * 1024];
        zsq0 = fmaf(a0, a0, zsq0);
        zsq0 = fmaf(a1, a1, zsq0);
        zA[i] = (ull)__float_as_uint(a0) | ((ull)__float_as_uint(a1) << 32);
        float c0 = z1p[(2 * i) * 1024];
        float c1 = z1p[(2 * i + 1) * 1024];
        zsq1 = fmaf(c0, c0, zsq1);
        zsq1 = fmaf(c1, c1, zsq1);
        zB[i] = (ull)__float_as_uint(c0) | ((ull)__float_as_uint(c1) << 32);
    }

    float best0 = 3.4e38f, best1 = 3.4e38f;
    int bi0 = 0, bi1 = 0;

    for (int c = 0; c < NCHUNK; c++) {   // ascending chunk order (tie policy!)
        __syncthreads();
        // Stage 128 codes (32 KB) into smem, float4-wide, fully coalesced.
        const float4* src = (const float4*)(E + c * CHUNK * DIM);
        float4* dst = (float4*)sE;
        #pragma unroll
        for (int i = 0; i < 16; i++) dst[t + i * 128] = src[t + i * 128];
        sEsq[t] = g_Esq[c * CHUNK + t];
        __syncthreads();

        #pragma unroll 2
        for (int k = 0; k < CHUNK; k += 2) {
            const ulonglong2* e2a = (const ulonglong2*)(sE + k * DIM);
            const ulonglong2* e2b = (const ulonglong2*)(sE + (k + 1) * DIM);
            // 8 independent FMA2 chains (2 rows x 2 codes x 2 accs).
            ull a0 = 0, a1 = 0, b0a = 0, b1a = 0;   // code k
            ull c0 = 0, c1 = 0, d0a = 0, d1a = 0;   // code k+1
            #pragma unroll
            for (int j = 0; j < 16; j++) {
                ulonglong2 ea = e2a[j];           // ld.shared.v2.u64 (broadcast)
                ulonglong2 eb = e2b[j];
                FMA2(a0,  zA[2 * j],     ea.x);
                FMA2(a1,  zA[2 * j + 1], ea.y);
                FMA2(b0a, zB[2 * j],     ea.x);
                FMA2(b1a, zB[2 * j + 1], ea.y);
                FMA2(c0,  zA[2 * j],     eb.x);
                FMA2(c1,  zA[2 * j + 1], eb.y);
                FMA2(d0a, zB[2 * j],     eb.x);
                FMA2(d1a, zB[2 * j + 1], eb.y);
            }
            // --- code k epilogue (exact R2 order) ---
            ull sa, sb;
            ADD2(sa, a0, a1);
            ADD2(sb, b0a, b1a);
            float s0 = __fadd_rn(__uint_as_float((unsigned)sa),
                                 __uint_as_float((unsigned)(sa >> 32)));
            float s1 = __fadd_rn(__uint_as_float((unsigned)sb),
                                 __uint_as_float((unsigned)(sb >> 32)));
            float esqA = sEsq[k];
            float dA0 = __fmaf_rn(-2.0f, s0, __fadd_rn(zsq0, esqA));
            float dA1 = __fmaf_rn(-2.0f, s1, __fadd_rn(zsq1, esqA));
            // --- code k+1 epilogue ---
            ull sc, sd;
            ADD2(sc, c0, c1);
            ADD2(sd, d0a, d1a);
            float s2 = __fadd_rn(__uint_as_float((unsigned)sc),
                                 __uint_as_float((unsigned)(sc >> 32)));
            float s3 = __fadd_rn(__uint_as_float((unsigned)sd),
                                 __uint_as_float((unsigned)(sd >> 32)));
            float esqB = sEsq[k + 1];
            float dB0 = __fmaf_rn(-2.0f, s2, __fadd_rn(zsq0, esqB));
            float dB1 = __fmaf_rn(-2.0f, s3, __fadd_rn(zsq1, esqB));

            // Branchless min updates, ascending k within the pair so ties
            // keep the lowest index (strict <). FMNMX carries best (lat 4);
            // FSETP/SEL carry the index off the critical path.
            const int kk = c * CHUNK + k;
            bool ltA0 = dA0 < best0;
            bool ltA1 = dA1 < best1;
            best0 = fminf(best0, dA0);
            best1 = fminf(best1, dA1);
            bi0 = ltA0 ? kk : bi0;
            bi1 = ltA1 ? kk : bi1;
            bool ltB0 = dB0 < best0;
            bool ltB1 = dB1 < best1;
            best0 = fminf(best0, dB0);
            best1 = fminf(best1, dB1);
            bi0 = ltB0 ? (kk + 1) : bi0;
            bi1 = ltB1 ? (kk + 1) : bi1;
        }
    }

    g_idx[n0] = bi0;
    g_idx[n1] = bi1;
    atomicAdd(&g_counts[bi0], 1);
    atomicAdd(&g_counts[bi1], 1);
}

// ---------------------------------------------------------------------------
// Kernel 3: gather Zq (straight-through, bit-mimicking fl(z + fl(e - z))),
// write transposed [B,C,H,W], accumulate sum((e - z)^2) for the losses.
// ---------------------------------------------------------------------------
__global__ void gather_kernel(const float* __restrict__ in,
                              const float* __restrict__ E,
                              float* __restrict__ out) {
    const int t = threadIdx.x;
    const int n = blockIdx.x * 256 + t;
    const int b = n >> 10, p = n & 1023;
    const int id = g_idx[n];

    float e[DIM];
    const float4* er = (const float4*)(E + id * DIM);
    #pragma unroll
    for (int i = 0; i < 16; i++) {
        float4 v = er[i];
        e[4 * i] = v.x; e[4 * i + 1] = v.y; e[4 * i + 2] = v.z; e[4 * i + 3] = v.w;
    }

    const float* zp = in + b * 65536 + p;
    float* zq = out + 1 + b * 65536 + p;  // Zq starts at out[1]
    float ls = 0.f;
    #pragma unroll
    for (int d = 0; d < DIM; d++) {
        float z = zp[d * 1024];
        float diff = __fsub_rn(e[d], z);          // ref: Zq_t - Ze_t in fp32
        ls = fmaf(diff, diff, ls);
        zq[d * 1024] = __fadd_rn(z, diff);        // ref: Ze + (Zq - Ze) in fp32
    }

    // Block-reduce loss partial, one double atomic per block.
    ls += __shfl_xor_sync(0xffffffffu, ls, 16);
    ls += __shfl_xor_sync(0xffffffffu, ls, 8);
    ls += __shfl_xor_sync(0xffffffffu, ls, 4);
    ls += __shfl_xor_sync(0xffffffffu, ls, 2);
    ls += __shfl_xor_sync(0xffffffffu, ls, 1);
    __shared__ float warpsum[8];
    if ((t & 31) == 0) warpsum[t >> 5] = ls;
    __syncthreads();
    if (t == 0) {
        float s = 0.f;
        #pragma unroll
        for (int w = 0; w < 8; w++) s += warpsum[w];
        atomicAdd(&g_loss, (double)s);
    }
}

// ---------------------------------------------------------------------------
// Kernel 4: perplexity from histogram + scalar outputs.
// ---------------------------------------------------------------------------
__global__ void finalize_kernel(float* __restrict__ out) {
    __shared__ float red[32];
    const int t = threadIdx.x;  // 1024 threads
    float cnt = (float)g_counts[t];
    float p = cnt * (1.0f / 65536.0f);
    float v = p * log2f(p + 1e-10f);

    v += __shfl_xor_sync(0xffffffffu, v, 16);
    v += __shfl_xor_sync(0xffffffffu, v, 8);
    v += __shfl_xor_sync(0xffffffffu, v, 4);
    v += __shfl_xor_sync(0xffffffffu, v, 2);
    v += __shfl_xor_sync(0xffffffffu, v, 1);
    if ((t & 31) == 0) red[t >> 5] = v;
    __syncthreads();
    if (t < 32) {
        float x = red[t];
        x += __shfl_xor_sync(0xffffffffu, x, 16);
        x += __shfl_xor_sync(0xffffffffu, x, 8);
        x += __shfl_xor_sync(0xffffffffu, x, 4);
        x += __shfl_xor_sync(0xffffffffu, x, 2);
        x += __shfl_xor_sync(0xffffffffu, x, 1);
        if (t == 0) {
            float entropy = -x;
            float perp = exp2f(entropy);
            float l = (float)(g_loss * (1.0 / 4194304.0));  // mean over B*H*W*D
            out[0] = l + 0.25f * l;          // q + BETA*e (q == e numerically)
            out[1 + N_ROWS * DIM]     = l;   // e_latent_loss
            out[1 + N_ROWS * DIM + 1] = l;   // q_latent_loss
            out[1 + N_ROWS * DIM + 2] = perp;
        }
    }
}

// ---------------------------------------------------------------------------
extern "C" void kernel_launch(void* const* d_in, const int* in_sizes, int n_in,
                              void* d_out, int out_size) {
    const float* in = (const float*)d_in[0];
    const float* E  = (const float*)d_in[1];
    float* out = (float*)d_out;

    prep_kernel<<<4, 256>>>(E);
    argmin_kernel<<<256, 128>>>(in, E);
    gather_kernel<<<256, 256>>>(in, E, out);
    finalize_kernel<<<1, 1024>>>(out);
}